// round 2
// baseline (speedup 1.0000x reference)
#include <cuda_runtime.h>
#include <cstdint>

// Problem constants
#define NN      512
#define BB      128
#define TT      1000
#define NINP    6
#define NSLICE  64      // N rows per CTA
#define BTILE   8       // batches per cluster
#define CLUST   8       // CTAs per cluster (N slices)
#define NCTA    128
#define NTHR    256

// SMEM layout (bytes). Dynamic smem, base 16B-aligned.
// Wp : [256 k2][64 cols] float2, cols interleaved: col (2*l)->n=l, (2*l+1)->n=l+32
#define WP_OFF   0
#define WP_BYTES (256*64*8)                 // 131072
// sT : [256 k2][8 b] float2, row stride 80B (64B data + 16B pad)
#define ST_OFF   (WP_OFF + WP_BYTES)        // 131072
#define ST_STRIDE 80
#define ST_BYTES (256*ST_STRIDE)            // 20480
// partials: [8 warp][8 b][64 n] float2
#define PART_OFF (ST_OFF + ST_BYTES)        // 151552
#define PART_BYTES (8*8*64*8)               // 32768
// xin: [8 b][6 j] float
#define XIN_OFF  (PART_OFF + PART_BYTES)    // 184320
// winp: [6 j][64 n] float
#define WI_OFF   (XIN_OFF + 256)            // 184576
#define WI_BYTES (6*64*4)                   // 1536
#define SMEM_TOTAL (WI_OFF + WI_BYTES)      // 186112

// global double-buffered state exchange (allowed: __device__ global array)
__device__ float g_sbuf[2][BB][NN];

__device__ __forceinline__ void ffma2(unsigned long long &d,
                                      unsigned long long a,
                                      unsigned long long b) {
    asm("fma.rn.f32x2 %0, %1, %2, %0;" : "+l"(d) : "l"(a), "l"(b));
}

__global__ void __cluster_dims__(CLUST, 1, 1) __launch_bounds__(NTHR, 1)
rnn_persistent_kernel(const float* __restrict__ u,
                      const float* __restrict__ rnoise,
                      const float* __restrict__ inoise,
                      const float* __restrict__ Wrec,
                      const float* __restrict__ Winp,
                      const float* __restrict__ yinit,
                      float* __restrict__ states)
{
    extern __shared__ char smem[];
    const int tid    = threadIdx.x;
    const int lane   = tid & 31;
    const int wid    = tid >> 5;
    const int cid    = blockIdx.x >> 3;   // cluster id  (batch group)
    const int rank   = blockIdx.x & 7;    // cta rank    (N slice)
    const int b_base = cid * BTILE;
    const int n_base = rank * NSLICE;

    // ---- one-time init: W_rec slice -> SMEM (interleaved float2 along k) ----
    for (int lin = tid; lin < NSLICE * 128; lin += NTHR) {
        int n_l = lin >> 7;           // 0..63
        int k4  = lin & 127;          // 0..127
        float4 w = *(const float4*)(Wrec + (size_t)(n_base + n_l) * NN + k4 * 4);
        int c = ((n_l & 31) << 1) | (n_l >> 5);   // interleaved column
        *(float2*)(smem + WP_OFF + (((2*k4    ) * 64 + c) << 3)) = make_float2(w.x, w.y);
        *(float2*)(smem + WP_OFF + (((2*k4 + 1) * 64 + c) << 3)) = make_float2(w.z, w.w);
    }
    // W_inp slice -> SMEM as winp[j][n]
    for (int lin = tid; lin < NINP * NSLICE; lin += NTHR) {
        int j = lin >> 6, n_l = lin & 63;
        *(float*)(smem + WI_OFF + lin * 4) = Winp[(size_t)(n_base + n_l) * NINP + j];
    }
    // s(0) = y_init broadcast over batches -> sT
    for (int k2 = tid; k2 < 256; k2 += NTHR) {
        float2 v = make_float2(yinit[2*k2], yinit[2*k2 + 1]);
        #pragma unroll
        for (int b = 0; b < BTILE; b++)
            *(float2*)(smem + ST_OFF + k2 * ST_STRIDE + b * 8) = v;
    }
    // states[:, 0, n_slice] = y_init
    for (int o = tid; o < BTILE * NSLICE; o += NTHR) {
        int b = o >> 6, n = o & 63;
        states[((size_t)(b_base + b) * TT) * NN + n_base + n] = yinit[n_base + n];
    }
    __syncthreads();

    const int b1 = tid >> 6;          // 0..3 (first output batch)
    const int n1 = tid & 63;          // output n within slice
    const int b2 = b1 + 4;            // second output batch

    for (int t = 0; t < TT - 1; t++) {
        const int nb = (t + 1) & 1;

        // -- prefetch per-step noise / input (consumed in epilogue, hidden under GEMM) --
        float rnA = rnoise[((size_t)(b_base + b1) * TT + t) * NN + n_base + n1];
        float rnB = rnoise[((size_t)(b_base + b2) * TT + t) * NN + n_base + n1];
        float xu = 0.f, xv = 0.f;
        if (tid < BTILE * NINP) {
            int bb = tid / NINP, jj = tid - bb * NINP;
            size_t off = ((size_t)(b_base + bb) * TT + t) * NINP + jj;
            xu = u[off]; xv = inoise[off];
        }

        // -------- GEMM partials: warp 'wid' covers k2 in [wid*32, wid*32+32) --------
        unsigned long long acc[16];
        #pragma unroll
        for (int i = 0; i < 16; i++) acc[i] = 0ull;
        {
            const char* wp = smem + WP_OFF + (size_t)(wid * 32) * 64 * 8;
            const char* sp = smem + ST_OFF + (size_t)(wid * 32) * ST_STRIDE;
            #pragma unroll 4
            for (int it = 0; it < 32; it++) {
                ulonglong2 wpair = *(const ulonglong2*)(wp + ((it * 64 + (lane << 1)) << 3));
                const unsigned long long wlo = wpair.x;   // n = lane
                const unsigned long long whi = wpair.y;   // n = lane + 32
                ulonglong2 s01 = *(const ulonglong2*)(sp + it * ST_STRIDE);
                ulonglong2 s23 = *(const ulonglong2*)(sp + it * ST_STRIDE + 16);
                ulonglong2 s45 = *(const ulonglong2*)(sp + it * ST_STRIDE + 32);
                ulonglong2 s67 = *(const ulonglong2*)(sp + it * ST_STRIDE + 48);
                ffma2(acc[0],  wlo, s01.x); ffma2(acc[1],  wlo, s01.y);
                ffma2(acc[2],  wlo, s23.x); ffma2(acc[3],  wlo, s23.y);
                ffma2(acc[4],  wlo, s45.x); ffma2(acc[5],  wlo, s45.y);
                ffma2(acc[6],  wlo, s67.x); ffma2(acc[7],  wlo, s67.y);
                ffma2(acc[8],  whi, s01.x); ffma2(acc[9],  whi, s01.y);
                ffma2(acc[10], whi, s23.x); ffma2(acc[11], whi, s23.y);
                ffma2(acc[12], whi, s45.x); ffma2(acc[13], whi, s45.y);
                ffma2(acc[14], whi, s67.x); ffma2(acc[15], whi, s67.y);
            }
        }
        // store partials: part[wid][b][n]
        {
            char* pb = smem + PART_OFF + (size_t)(wid * BTILE) * 64 * 8;
            #pragma unroll
            for (int b = 0; b < BTILE; b++) {
                *(unsigned long long*)(pb + ((b * 64 + lane     ) << 3)) = acc[b];
                *(unsigned long long*)(pb + ((b * 64 + lane + 32) << 3)) = acc[8 + b];
            }
        }
        if (tid < BTILE * NINP)
            *(float*)(smem + XIN_OFF + tid * 4) = xu + xv;
        __syncthreads();

        // -------- reduction + state update: 2 outputs/thread --------
        #pragma unroll
        for (int half = 0; half < 2; half++) {
            const int b  = half ? b2 : b1;
            const int n  = n1;
            const float rn = half ? rnB : rnA;
            float sx = 0.f, sy = 0.f;
            #pragma unroll
            for (int w = 0; w < 8; w++) {
                float2 p = *(const float2*)(smem + PART_OFF + (((w * BTILE + b) * 64 + n) << 3));
                sx += p.x; sy += p.y;
            }
            float pre = sx + sy;
            #pragma unroll
            for (int j = 0; j < NINP; j++)
                pre = fmaf(*(const float*)(smem + XIN_OFF + (b * NINP + j) * 4),
                           *(const float*)(smem + WI_OFF + (j * 64 + n) * 4), pre);
            const int ng = n_base + n;
            float sold = *(const float*)(smem + ST_OFF + (ng >> 1) * ST_STRIDE
                                         + b * 8 + (ng & 1) * 4);
            float v    = fmaxf(pre, 0.f) + rn;
            float snew = 0.9f * sold + 0.1f * v;
            states[((size_t)(b_base + b) * TT + (t + 1)) * NN + ng] = snew;
            __stcg(&g_sbuf[nb][b_base + b][ng], snew);
        }

        // -------- cluster barrier: all slices of s(t+1) published --------
        asm volatile("barrier.cluster.arrive.aligned;" ::: "memory");
        asm volatile("barrier.cluster.wait.aligned;"   ::: "memory");

        // -------- reload full s(t+1) (8 batches x 512) into sT (transposed) --------
        {
            const int b_l  = tid & 7;
            const int k4b  = tid >> 3;     // 0..31
            const float* src = &g_sbuf[nb][b_base + b_l][0];
            #pragma unroll
            for (int i = 0; i < 4; i++) {
                int k4 = k4b + i * 32;
                float4 v = __ldcg((const float4*)(src + k4 * 4));
                *(float2*)(smem + ST_OFF + (2*k4    ) * ST_STRIDE + b_l * 8) = make_float2(v.x, v.y);
                *(float2*)(smem + ST_OFF + (2*k4 + 1) * ST_STRIDE + b_l * 8) = make_float2(v.z, v.w);
            }
        }
        __syncthreads();
    }
}

// outputs[b,t] = dot(states[b,t,:], W_out)  — memory-bound streaming pass
__global__ void __launch_bounds__(256, 1)
readout_kernel(const float* __restrict__ states,
               const float* __restrict__ wout,
               float* __restrict__ outp)
{
    const int row  = blockIdx.x * 8 + (threadIdx.x >> 5);   // b*T + t
    const int lane = threadIdx.x & 31;
    if (row >= BB * TT) return;
    const float4* sp = (const float4*)(states + (size_t)row * NN);
    float acc = 0.f;
    #pragma unroll
    for (int i = 0; i < 4; i++) {
        float4 s = sp[lane + 32 * i];
        float4 w = *(const float4*)(wout + (lane + 32 * i) * 4);
        acc = fmaf(s.x, w.x, acc);
        acc = fmaf(s.y, w.y, acc);
        acc = fmaf(s.z, w.z, acc);
        acc = fmaf(s.w, w.w, acc);
    }
    #pragma unroll
    for (int off = 16; off; off >>= 1)
        acc += __shfl_xor_sync(0xffffffffu, acc, off);
    if (lane == 0) outp[row] = acc;
}

extern "C" void kernel_launch(void* const* d_in, const int* in_sizes, int n_in,
                              void* d_out, int out_size)
{
    const float* u      = (const float*)d_in[0];
    const float* rnois  = (const float*)d_in[1];
    const float* inois  = (const float*)d_in[2];
    const float* wrec   = (const float*)d_in[3];
    const float* winp   = (const float*)d_in[4];
    const float* wout   = (const float*)d_in[5];
    const float* yini   = (const float*)d_in[6];

    float* states = (float*)d_out;                       // (B, T, N)
    float* outp   = states + (size_t)BB * TT * NN;       // (B, T, 1)

    cudaFuncSetAttribute(rnn_persistent_kernel,
                         cudaFuncAttributeMaxDynamicSharedMemorySize, SMEM_TOTAL);

    rnn_persistent_kernel<<<NCTA, NTHR, SMEM_TOTAL>>>(u, rnois, inois,
                                                      wrec, winp, yini, states);
    readout_kernel<<<(BB * TT) / 8, 256>>>(states, wout, outp);
}